// round 14
// baseline (speedup 1.0000x reference)
#include <cuda_runtime.h>
#include <cuda_bf16.h>
#include <math.h>
#include <stdint.h>

#define NHEADS 8
#define EMB    64
#define FA     256
#define FB     256
#define BATCH  2
#define SEQ    2048
#define HFB    (NHEADS*FB)   // 2048

// q pre-scale: 0.125 (1/sqrt(64)) * log2(e) so S is in log2 domain
#define QSCALE 0.18033688011112042f
// l1 compensation: |s_nat| = |s_log2| * ln2
#define L1SCALE (0.6931471805599453f / 33554432.0f)   // ln2 / (8*2048*2048)

// ---------------- scratch (device globals; no allocations allowed) ----------
__device__ __nv_bfloat16 g_qh[(size_t)BATCH*NHEADS*SEQ*EMB];
__device__ __nv_bfloat16 g_ql[(size_t)BATCH*NHEADS*SEQ*EMB];
__device__ __nv_bfloat16 g_kh[(size_t)BATCH*NHEADS*SEQ*EMB];
__device__ __nv_bfloat16 g_kl[(size_t)BATCH*NHEADS*SEQ*EMB];
__device__ __nv_bfloat16 g_vh[(size_t)BATCH*FB*SEQ];
__device__ __nv_bfloat16 g_vl[(size_t)BATCH*FB*SEQ];
__device__ __nv_bfloat16 g_wh[(size_t)FA*HFB];
__device__ __nv_bfloat16 g_wl[(size_t)FA*HFB];
__device__ __nv_bfloat16 g_fh[(size_t)BATCH*SEQ*HFB];
__device__ __nv_bfloat16 g_fl[(size_t)BATCH*SEQ*HFB];

// ============================ helpers ========================================
__device__ __forceinline__ uint32_t smem_u32(const void* p) {
    uint32_t a;
    asm("{ .reg .u64 t; cvta.to.shared.u64 t, %1; cvt.u32.u64 %0, t; }" : "=r"(a) : "l"(p));
    return a;
}
#define CP_ASYNC16(dst, src) \
    asm volatile("cp.async.cg.shared.global [%0], [%1], 16;" :: "r"(dst), "l"(src))
#define CP_COMMIT() asm volatile("cp.async.commit_group;" ::: "memory")
#define CP_WAIT(n)  asm volatile("cp.async.wait_group %0;" :: "n"(n) : "memory")

#define LDSM4(r, addr) \
    asm volatile("ldmatrix.sync.aligned.m8n8.x4.shared.b16 {%0,%1,%2,%3}, [%4];" \
        : "=r"((r)[0]), "=r"((r)[1]), "=r"((r)[2]), "=r"((r)[3]) : "r"(addr))

#define MMA16816(d, a, b0, b1)                                                  \
    asm volatile("mma.sync.aligned.m16n8k16.row.col.f32.bf16.bf16.f32 "         \
        "{%0,%1,%2,%3}, {%4,%5,%6,%7}, {%8,%9}, {%0,%1,%2,%3};"                 \
        : "+f"((d)[0]), "+f"((d)[1]), "+f"((d)[2]), "+f"((d)[3])                \
        : "r"((a)[0]), "r"((a)[1]), "r"((a)[2]), "r"((a)[3]), "r"(b0), "r"(b1))

__device__ __forceinline__ void cvt_hl(float v, __nv_bfloat16& h, __nv_bfloat16& l) {
    h = __float2bfloat16_rn(v);
    l = __float2bfloat16_rn(v - __bfloat162float(h));
}
__device__ __forceinline__ uint32_t pack2(__nv_bfloat16 a, __nv_bfloat16 b) {
    return ((uint32_t)__bfloat16_as_ushort(b) << 16) | (uint32_t)__bfloat16_as_ushort(a);
}
__device__ __forceinline__ float ex2(float x) {
    float y; asm("ex2.approx.f32 %0, %1;" : "=f"(y) : "f"(x)); return y;
}

// ---- tile stage format (proven): per 16-k slice a row is 64B:
// [hi: 2 x 16B chunks | lo: 2 x 16B chunks], chunk' = chunk ^ ((row>>1)&3).
template<int R, int NS, int NT>
__device__ __forceinline__ void issue_tile(uint32_t sb,
    const __nv_bfloat16* __restrict__ Gh, const __nv_bfloat16* __restrict__ Gl, int ld)
{
    const int tid = threadIdx.x;
    constexpr int CPT = (R * NS * 4) / NT;
    #pragma unroll
    for (int p = 0; p < CPT; p++) {
        int id  = tid + p * NT;
        int s   = id / (R * 4);
        int rem = id - s * (R * 4);
        int r   = rem >> 2, cc = rem & 3;
        const __nv_bfloat16* src = (cc < 2 ? Gh : Gl)
            + (size_t)r * ld + s * 16 + ((cc & 1) << 3);
        uint32_t dst = sb + s * (R * 64) + r * 64 + ((cc ^ ((r >> 1) & 3)) << 4);
        CP_ASYNC16(dst, src);
    }
}

// A frag, single 16-row m-frag (rows wm..wm+15)
__device__ __forceinline__ void lda_frag1(uint32_t stb, int wm, int lane,
                                          uint32_t ah[4], uint32_t al[4])
{
    int r  = wm + (lane & 15);
    int ch = (lane >> 4) & 1;
    uint32_t rb = stb + r * 64;
    LDSM4(ah, rb + (((ch)     ^ ((r >> 1) & 3)) << 4));
    LDSM4(al, rb + (((ch + 2) ^ ((r >> 1) & 3)) << 4));
}
// B frag, single 16-row n-frag (rows wn..wn+15)
__device__ __forceinline__ void ldb_frag1(uint32_t stb, int wn, int lane,
                                          uint32_t bh_[4], uint32_t bl_[4])
{
    int r  = wn + (lane & 7) + ((lane & 16) ? 8 : 0);
    int ch = (lane >> 3) & 1;
    uint32_t rb = stb + r * 64;
    LDSM4(bh_, rb + (((ch)     ^ ((r >> 1) & 3)) << 4));
    LDSM4(bl_, rb + (((ch + 2) ^ ((r >> 1) & 3)) << 4));
}
// B frags, 32 rows (wn..wn+31)
__device__ __forceinline__ void ldb_frag(uint32_t stb, int wn, int lane,
                                         uint32_t bh_[2][4], uint32_t bl_[2][4])
{
    #pragma unroll
    for (int nb = 0; nb < 2; nb++) {
        int r  = wn + nb * 16 + (lane & 7) + ((lane & 16) ? 8 : 0);
        int ch = (lane >> 3) & 1;
        uint32_t rb = stb + r * 64;
        LDSM4(bh_[nb], rb + (((ch)     ^ ((r >> 1) & 3)) << 4));
        LDSM4(bl_[nb], rb + (((ch + 2) ^ ((r >> 1) & 3)) << 4));
    }
}

// ---------------- fused attention smem layout (dynamic) ----------------------
#define OQ   0          // 64 x 4 stages  = 16384
#define OK_  16384      // 128 x 4 stages = 32768
#define OP   49152      // 64 x 8 stages  = 32768
#define OV0  81920      // 128 x 8 stages = 65536
#define OV1  147456     // 128 x 8 stages = 65536
#define OL   212992     // 64 floats
#define ORED 213248     // 16 floats
#define SMEM_FUSED 213504

// ============ fused: pre + softmax(+l1) + feat, per (bh, 64-q tile) ==========
// 512 threads, 16 warps as 2(m) x 8(n): wm = (wid>>3)*32 (2 m-frags of 16),
// S: wn_s = (wid&7)*16 ; PV: warp covers cols (wid&7)*32 of 256.
__global__ __launch_bounds__(512, 1) void attn_fused_kernel(float* __restrict__ l1)
{
    extern __shared__ char SM[];
    const uint32_t SB = smem_u32(SM);
    const int tid = threadIdx.x, lane = tid & 31, wid = tid >> 5;
    const int gm = wid >> 3, gn = wid & 7;
    const int wm = gm * 32;
    const int wn_s = gn * 16;
    const int qt = blockIdx.x, bh = blockIdx.y;
    const int b = bh >> 3, h = bh & 7;
    const int qbase = qt * 64;
    float* slf = (float*)(SM + OL);
    float* red = (float*)(SM + ORED);

    const __nv_bfloat16* Qh = g_qh + ((size_t)bh * SEQ + qbase) * EMB;
    const __nv_bfloat16* Ql = g_ql + ((size_t)bh * SEQ + qbase) * EMB;
    const __nv_bfloat16* Kh = g_kh + (size_t)bh * SEQ * EMB;
    const __nv_bfloat16* Kl = g_kl + (size_t)bh * SEQ * EMB;
    const __nv_bfloat16* Vh0 = g_vh + (size_t)b * FB * SEQ;
    const __nv_bfloat16* Vl0 = g_vl + (size_t)b * FB * SEQ;
    const __nv_bfloat16* Vh1 = Vh0 + (size_t)128 * SEQ;
    const __nv_bfloat16* Vl1 = Vl0 + (size_t)128 * SEQ;

    // PV: this warp's V half and row base within it
    const uint32_t vbase = SB + ((gn < 4) ? OV0 : OV1);
    const int vrow = (gn & 3) * 32;
    const int cbase = gn * 32;     // global f column base (0..224)

    if (tid < 64) slf[tid] = 0.0f;

    // prologue: G0 = Q + K_0 ; G1 = V_0 (both halves)
    issue_tile<64, 4, 512>(SB + OQ, Qh, Ql, EMB);
    issue_tile<128, 4, 512>(SB + OK_, Kh, Kl, EMB);
    CP_COMMIT();
    issue_tile<128, 8, 512>(SB + OV0, Vh0, Vl0, SEQ);
    issue_tile<128, 8, 512>(SB + OV1, Vh1, Vl1, SEQ);
    CP_COMMIT();

    float oacc[2][4][4] = {};
    float l1acc = 0.0f;

    for (int j = 0; j < 16; j++) {
        const int jn = (j + 1) & 15;    // wrap-around prefetch: uniform wait counts
        CP_WAIT(1);                     // K_j (and Q on j=0) arrived; V_j may fly
        __syncthreads();                // (a) K visible; P(j-1) fully consumed

        // ---- S = Q x K^T (64 x 128, K=64), bf16x3, log2-domain ----
        float sacc[2][2][4] = {};
        #pragma unroll
        for (int ks = 0; ks < 4; ks++) {
            uint32_t qh0[4], ql0[4], qh1[4], ql1[4], kbh[4], kbl[4];
            lda_frag1(SB + OQ + ks * 4096, wm,      lane, qh0, ql0);
            lda_frag1(SB + OQ + ks * 4096, wm + 16, lane, qh1, ql1);
            ldb_frag1(SB + OK_ + ks * 8192, wn_s, lane, kbh, kbl);
            #pragma unroll
            for (int ni = 0; ni < 2; ni++) {
                const int o = ni << 1;
                MMA16816(sacc[0][ni], qh0, kbh[o], kbh[o + 1]);
                MMA16816(sacc[0][ni], qh0, kbl[o], kbl[o + 1]);
                MMA16816(sacc[0][ni], ql0, kbh[o], kbh[o + 1]);
                MMA16816(sacc[1][ni], qh1, kbh[o], kbh[o + 1]);
                MMA16816(sacc[1][ni], qh1, kbl[o], kbl[o + 1]);
                MMA16816(sacc[1][ni], ql1, kbh[o], kbh[o + 1]);
            }
        }

        // ---- convert: |s| -> l1, exp2 -> P hi/lo smem + row sums ----
        #pragma unroll
        for (int mi = 0; mi < 2; mi++) {
            const int r0 = wm + mi * 16 + (lane >> 2);
            const int r1 = r0 + 8;
            float rs0 = 0.0f, rs1 = 0.0f;
            #pragma unroll
            for (int ni = 0; ni < 2; ni++) {
                const int c  = wn_s + ni * 8 + ((lane & 3) << 1);
                const int st = c >> 4, kk = c & 15;
                const int ch = kk >> 3, intra = (kk & 7) * 2;
                float s0 = sacc[mi][ni][0], s1 = sacc[mi][ni][1];
                float s2 = sacc[mi][ni][2], s3 = sacc[mi][ni][3];
                l1acc += fabsf(s0) + fabsf(s1) + fabsf(s2) + fabsf(s3);
                float p0 = ex2(s0), p1 = ex2(s1);
                float p2 = ex2(s2), p3 = ex2(s3);
                rs0 += p0 + p1; rs1 += p2 + p3;
                __nv_bfloat16 H0, L0, H1, L1;
                cvt_hl(p0, H0, L0); cvt_hl(p1, H1, L1);
                const uint32_t b0 = OP + st * 4096 + r0 * 64;
                *(uint32_t*)(SM + b0 + (((ch)     ^ ((r0 >> 1) & 3)) << 4) + intra) = pack2(H0, H1);
                *(uint32_t*)(SM + b0 + (((ch + 2) ^ ((r0 >> 1) & 3)) << 4) + intra) = pack2(L0, L1);
                cvt_hl(p2, H0, L0); cvt_hl(p3, H1, L1);
                const uint32_t b1 = OP + st * 4096 + r1 * 64;
                *(uint32_t*)(SM + b1 + (((ch)     ^ ((r1 >> 1) & 3)) << 4) + intra) = pack2(H0, H1);
                *(uint32_t*)(SM + b1 + (((ch + 2) ^ ((r1 >> 1) & 3)) << 4) + intra) = pack2(L0, L1);
            }
            rs0 += __shfl_xor_sync(0xffffffffu, rs0, 1);
            rs0 += __shfl_xor_sync(0xffffffffu, rs0, 2);
            rs1 += __shfl_xor_sync(0xffffffffu, rs1, 1);
            rs1 += __shfl_xor_sync(0xffffffffu, rs1, 2);
            if ((lane & 3) == 0) {
                atomicAdd(&slf[r0], rs0);
                atomicAdd(&slf[r1], rs1);
            }
        }

        CP_WAIT(0);                     // V_j arrived (only group left)
        __syncthreads();                // (b) publish P_j + slf; K_j consumed

        // K_{j+1} prefetch flies during the long PV phase
        issue_tile<128, 4, 512>(SB + OK_, Kh + (size_t)jn * 128 * EMB,
                                Kl + (size_t)jn * 128 * EMB, EMB);
        CP_COMMIT();                    // group [K_{j+1}]

        // ---- PV: O += P x V^T (this warp: 32 m-rows x 32 f-cols) ----
        #pragma unroll
        for (int ks = 0; ks < 8; ks++) {
            uint32_t ph0[4], pl0[4], ph1[4], pl1[4];
            lda_frag1(SB + OP + ks * 4096, wm,      lane, ph0, pl0);
            lda_frag1(SB + OP + ks * 4096, wm + 16, lane, ph1, pl1);
            uint32_t vh_[2][4], vl_[2][4];
            ldb_frag(vbase + ks * 8192, vrow, lane, vh_, vl_);
            #pragma unroll
            for (int ni = 0; ni < 4; ni++) {
                const int g = ni >> 1, o = (ni & 1) << 1;
                MMA16816(oacc[0][ni], ph0, vh_[g][o], vh_[g][o + 1]);
                MMA16816(oacc[0][ni], ph0, vl_[g][o], vl_[g][o + 1]);
                MMA16816(oacc[0][ni], pl0, vh_[g][o], vh_[g][o + 1]);
                MMA16816(oacc[1][ni], ph1, vh_[g][o], vh_[g][o + 1]);
                MMA16816(oacc[1][ni], ph1, vl_[g][o], vl_[g][o + 1]);
                MMA16816(oacc[1][ni], pl1, vh_[g][o], vh_[g][o + 1]);
            }
        }
        __syncthreads();                // (c) V_j consumed; P_j consumed
        issue_tile<128, 8, 512>(SB + OV0, Vh0 + jn * 128, Vl0 + jn * 128, SEQ);
        issue_tile<128, 8, 512>(SB + OV1, Vh1 + jn * 128, Vl1 + jn * 128, SEQ);
        CP_COMMIT();                    // group [V_{j+1}]
    }

    CP_WAIT(0);
    __syncthreads();

    // ---- epilogue: O / l -> feat hi/lo ----
    #pragma unroll
    for (int mi = 0; mi < 2; mi++) {
        const int r0 = wm + mi * 16 + (lane >> 2);
        const float inv0 = 1.0f / slf[r0];
        const float inv1 = 1.0f / slf[r0 + 8];
        #pragma unroll
        for (int ni = 0; ni < 4; ni++) {
            const float* a = oacc[mi][ni];
            const int c = cbase + ni * 8 + ((lane & 3) << 1);
            const size_t d0 = ((size_t)b * SEQ + qbase + r0) * HFB + h * FB + c;
            const size_t d1 = ((size_t)b * SEQ + qbase + r0 + 8) * HFB + h * FB + c;
            float v0 = a[0] * inv0, v1 = a[1] * inv0;
            float v2 = a[2] * inv1, v3 = a[3] * inv1;
            __nv_bfloat16 H0, L0, H1, L1;
            cvt_hl(v0, H0, L0); cvt_hl(v1, H1, L1);
            *(uint32_t*)(g_fh + d0) = pack2(H0, H1);
            *(uint32_t*)(g_fl + d0) = pack2(L0, L1);
            cvt_hl(v2, H0, L0); cvt_hl(v3, H1, L1);
            *(uint32_t*)(g_fh + d1) = pack2(H0, H1);
            *(uint32_t*)(g_fl + d1) = pack2(L0, L1);
        }
    }

    // ---- l1 reduction (log2-domain sums, scaled by ln2) ----
    #pragma unroll
    for (int o = 16; o > 0; o >>= 1)
        l1acc += __shfl_xor_sync(0xffffffffu, l1acc, o);
    if (lane == 0) red[wid] = l1acc;
    __syncthreads();
    if (tid == 0) {
        float t = 0.0f;
        #pragma unroll
        for (int w = 0; w < 16; w++) t += red[w];
        atomicAdd(&l1[b], t * L1SCALE);
    }
}

// ---------------- tiny init --------------------------------------------------
__global__ void zero_l1_kernel(float* l1) {
    if (threadIdx.x < BATCH) l1[threadIdx.x] = 0.0f;
}

// ---------------- conv: z_b and W_c -> bf16 hi/lo ----------------------------
__global__ __launch_bounds__(256) void conv_kernel(const float* __restrict__ zb,
                                                   const float* __restrict__ Wc)
{
    const int NZ = BATCH * FB * SEQ / 4;
    const int NW = FA * HFB / 4;
    int i = blockIdx.x * 256 + threadIdx.x;
    if (i < NZ) {
        float4 v = ((const float4*)zb)[i];
        __nv_bfloat16 h0,l0,h1,l1,h2,l2,h3,l3;
        cvt_hl(v.x,h0,l0); cvt_hl(v.y,h1,l1); cvt_hl(v.z,h2,l2); cvt_hl(v.w,h3,l3);
        ((uint2*)g_vh)[i] = make_uint2(pack2(h0,h1), pack2(h2,h3));
        ((uint2*)g_vl)[i] = make_uint2(pack2(l0,l1), pack2(l2,l3));
    } else if (i < NZ + NW) {
        int j = i - NZ;
        float4 v = ((const float4*)Wc)[j];
        __nv_bfloat16 h0,l0,h1,l1,h2,l2,h3,l3;
        cvt_hl(v.x,h0,l0); cvt_hl(v.y,h1,l1); cvt_hl(v.z,h2,l2); cvt_hl(v.w,h3,l3);
        ((uint2*)g_wh)[j] = make_uint2(pack2(h0,h1), pack2(h2,h3));
        ((uint2*)g_wl)[j] = make_uint2(pack2(l0,l1), pack2(l2,l3));
    }
}

// ---------------- embed: fp32 SIMT GEMM, epilogue -> qT/kT bf16 hi/lo --------
#define BM 128
#define BN 128
#define BK 8
#define TM 8
#define TN 8
__global__ __launch_bounds__(256) void embed_kernel(
    const float* __restrict__ Wa, const float* __restrict__ za,
    const float* __restrict__ Wb, const float* __restrict__ zb)
{
    const int bz = blockIdx.z;
    const int b = bz >> 1, sel = bz & 1;
    const float* __restrict__ A  = sel ? Wb : Wa;                       // [512 x 256]
    const float* __restrict__ Bm = (sel ? zb : za) + (size_t)b*FA*SEQ;  // [256 x 2048]
    __nv_bfloat16* __restrict__ Oh = sel ? g_kh : g_qh;
    __nv_bfloat16* __restrict__ Ol = sel ? g_kl : g_ql;
    const float scl = sel ? 1.0f : QSCALE;

    __shared__ float As[BK][BM];
    __shared__ float Bs[BK][BN];

    const int tid = threadIdx.x;
    const int m0 = blockIdx.y * BM;
    const int n0 = blockIdx.x * BN;
    const int K = FA;
    const int ty = tid >> 4, tx = tid & 15;

    float acc[TM][TN] = {};

    for (int k0 = 0; k0 < K; k0 += BK) {
        {
            const int mm = tid >> 1, kk = (tid & 1) * 4;
            float4 v = *(const float4*)&A[(size_t)(m0 + mm) * K + k0 + kk];
            As[kk + 0][mm] = v.x; As[kk + 1][mm] = v.y;
            As[kk + 2][mm] = v.z; As[kk + 3][mm] = v.w;
        }
        {
            const int kk = tid >> 5, nn = (tid & 31) * 4;
            *(float4*)&Bs[kk][nn] = *(const float4*)&Bm[(size_t)(k0 + kk) * SEQ + n0 + nn];
        }
        __syncthreads();
        #pragma unroll
        for (int kk = 0; kk < BK; kk++) {
            float a[TM], bb[TN];
            *(float4*)&a[0]  = *(const float4*)&As[kk][ty * TM];
            *(float4*)&a[4]  = *(const float4*)&As[kk][ty * TM + 4];
            *(float4*)&bb[0] = *(const float4*)&Bs[kk][tx * TN];
            *(float4*)&bb[4] = *(const float4*)&Bs[kk][tx * TN + 4];
            #pragma unroll
            for (int i = 0; i < TM; i++)
                #pragma unroll
                for (int j = 0; j < TN; j++)
                    acc[i][j] += a[i] * bb[j];
        }
        __syncthreads();
    }
    // transposed epilogue: m = o = h*64+e -> write [bh][n][e]
    const int mbase = m0 + ty * TM;
    const int h = mbase >> 6, e0 = mbase & 63;
    const size_t bh = (size_t)(b * NHEADS + h);
    #pragma unroll
    for (int j = 0; j < TN; j++) {
        const int n = n0 + tx * TN + j;
        uint32_t hw[4], lw[4];
        #pragma unroll
        for (int p = 0; p < 4; p++) {
            __nv_bfloat16 ha, la, hb, lb;
            cvt_hl(acc[2*p][j] * scl, ha, la);
            cvt_hl(acc[2*p+1][j] * scl, hb, lb);
            hw[p] = pack2(ha, hb); lw[p] = pack2(la, lb);
        }
        const size_t dst = (bh * SEQ + n) * EMB + e0;
        *(uint4*)(Oh + dst) = make_uint4(hw[0], hw[1], hw[2], hw[3]);
        *(uint4*)(Ol + dst) = make_uint4(lw[0], lw[1], lw[2], lw[3]);
    }
}

// ---------------- out: mma.sync bf16x3, K=2048, fp32 out ---------------------
#define ISSUE_STAGE(st, k0)                                                     \
    do {                                                                        \
        _Pragma("unroll")                                                       \
        for (int p = 0; p < 4; p++) {                                           \
            int id = tid + (p << 8);                                            \
            int isB = id >> 9;                                                  \
            int rem = id & 511;                                                 \
            int r = rem >> 2, cc = rem & 3;                                     \
            const __nv_bfloat16* src =                                          \
                (isB ? (cc < 2 ? Bh : Bl) : (cc < 2 ? Ah : Al))                 \
                + (size_t)r * (isB ? ldb : lda) + (k0) + ((cc & 1) << 3);       \
            uint32_t dst = sb + (st) * 16384 + isB * 8192 + r * 64              \
                         + ((cc ^ ((r >> 1) & 3)) << 4);                        \
            CP_ASYNC16(dst, src);                                               \
        }                                                                       \
    } while (0)

__device__ __forceinline__ void mma_nt_128(
    const __nv_bfloat16* __restrict__ Ah, const __nv_bfloat16* __restrict__ Al, int lda,
    const __nv_bfloat16* __restrict__ Bh, const __nv_bfloat16* __restrict__ Bl, int ldb,
    int K, float acc[4][4][4], unsigned char* sbuf)
{
    const int tid  = threadIdx.x;
    const int lane = tid & 31;
    const int wid  = tid >> 5;
    const int wm   = (wid >> 2) * 64;
    const int wn   = (wid & 3) * 32;
    const uint32_t sb = smem_u32(sbuf);

    #pragma unroll
    for (int mi = 0; mi < 4; mi++)
        #pragma unroll
        for (int ni = 0; ni < 4; ni++)
            #pragma unroll
            for (int q = 0; q < 4; q++) acc[mi][ni][q] = 0.0f;

    const int nst = K >> 4;
    ISSUE_STAGE(0, 0);
    CP_COMMIT();

    for (int s = 0; s < nst; s++) {
        if (s + 1 < nst) {
            ISSUE_STAGE((s + 1) & 1, (s + 1) << 4);
            CP_COMMIT();
            CP_WAIT(1);
        } else {
            CP_WAIT(0);
        }
        __syncthreads();

        const uint32_t stb = sb + (uint32_t)(s & 1) * 16384;
        uint32_t ah[4][4], al[4][4], bhf[2][4], blf[2][4];
        #pragma unroll
        for (int mi = 0; mi < 4; mi++) {
            int r  = wm + mi * 16 + (lane & 15);
            int ch = (lane >> 4) & 1;
            uint32_t rb = stb + r * 64;
            LDSM4(ah[mi], rb + (((ch)     ^ ((r >> 1) & 3)) << 4));
            LDSM4(al[mi], rb + (((ch + 2) ^ ((r >> 1) & 3)) << 4));
        }
        #pragma unroll
        for (int nb = 0; nb < 2; nb++) {
            int r  = wn + nb * 16 + (lane & 7) + ((lane & 16) ? 8 : 0);
            int ch = (lane >> 3) & 1;
            uint32_t rb = stb + 8192 + r * 64;
            LDSM4(bhf[nb], rb + (((ch)     ^ ((r >> 1) & 3)) << 4));
            LDSM4(blf[nb], rb + (((ch + 2) ^ ((r >> 1) & 3)) << 4));
        }
        #pragma unroll
        for (int mi = 0; mi < 4; mi++)
            #pragma unroll
            for (int ni = 0; ni < 4; ni++) {
                const int g = ni >> 1, o = (ni & 1) << 1;
                MMA16816(acc[mi][ni], ah[mi], bhf[g][o], bhf[g][o + 1]);
                MMA16816(acc[mi][ni], ah[mi], blf[g][o], blf[g][o + 1]);
                MMA16816(acc[mi][ni], al[mi], bhf[g][o], bhf[g][o + 1]);
            }
        __syncthreads();
    }
}

__global__ __launch_bounds__(256) void out_mma_kernel(float* __restrict__ out)
{
    __shared__ __align__(16) unsigned char sbuf[2][16384];
    const int tid = threadIdx.x, lane = tid & 31, wid = tid >> 5;
    const int b = blockIdx.z;
    const int m0 = blockIdx.y * 128;
    const int n0 = blockIdx.x * 128;

    const __nv_bfloat16* Ah = g_fh + ((size_t)b * SEQ + m0) * HFB;
    const __nv_bfloat16* Al = g_fl + ((size_t)b * SEQ + m0) * HFB;
    const __nv_bfloat16* Bh = g_wh + (size_t)n0 * HFB;
    const __nv_bfloat16* Bl = g_wl + (size_t)n0 * HFB;

    float acc[4][4][4];
    mma_nt_128(Ah, Al, HFB, Bh, Bl, HFB, HFB, acc, &sbuf[0][0]);

    const int wm = (wid >> 2) * 64, wn = (wid & 3) * 32;
    #pragma unroll
    for (int mi = 0; mi < 4; mi++) {
        #pragma unroll
        for (int ni = 0; ni < 4; ni++) {
            const int r0 = m0 + wm + mi * 16 + (lane >> 2);
            const int c  = n0 + wn + ni * 8 + ((lane & 3) << 1);
            *(float2*)(out + ((size_t)b * SEQ + r0) * FA + c) =
                make_float2(acc[mi][ni][0], acc[mi][ni][1]);
            *(float2*)(out + ((size_t)b * SEQ + r0 + 8) * FA + c) =
                make_float2(acc[mi][ni][2], acc[mi][ni][3]);
        }
    }
}

// ---------------- launch -----------------------------------------------------
extern "C" void kernel_launch(void* const* d_in, const int* in_sizes, int n_in,
                              void* d_out, int out_size)
{
    const float* z_a = (const float*)d_in[0];   // [2, 256, 2048]
    const float* z_b = (const float*)d_in[1];   // [2, 256, 2048]
    const float* W_a = (const float*)d_in[2];   // [512, 256]
    const float* W_b = (const float*)d_in[3];   // [512, 256]
    const float* W_c = (const float*)d_in[4];   // [256, 2048]
    float* out = (float*)d_out;                 // [2, 2048, 256] then l1 [2]
    float* l1  = out + (size_t)BATCH * SEQ * FA;

    cudaFuncSetAttribute(attn_fused_kernel,
                         cudaFuncAttributeMaxDynamicSharedMemorySize, SMEM_FUSED);

    zero_l1_kernel<<<1, 32>>>(l1);

    {
        const int nchunks = (BATCH * FB * SEQ + FA * HFB) / 4;
        conv_kernel<<<(nchunks + 255) / 256, 256>>>(z_b, W_c);
    }
    {
        dim3 grid(SEQ / BN, (NHEADS * EMB) / BM, BATCH * 2);
        embed_kernel<<<grid, 256>>>(W_a, z_a, W_b, z_b);
    }
    {
        dim3 grid(SEQ / 64, BATCH * NHEADS);
        attn_fused_kernel<<<grid, 512, SMEM_FUSED>>>(l1);
    }
    {
        dim3 grid(FA / 128, SEQ / 128, BATCH);
        out_mma_kernel<<<grid, 256>>>(out);
    }
}

// round 15
// speedup vs baseline: 1.2632x; 1.2632x over previous
#include <cuda_runtime.h>
#include <cuda_bf16.h>
#include <math.h>
#include <stdint.h>

#define NHEADS 8
#define EMB    64
#define FA     256
#define FB     256
#define BATCH  2
#define SEQ    2048
#define HFB    (NHEADS*FB)   // 2048

// q pre-scale: 0.125 (1/sqrt(64)) * log2(e) so S is in log2 domain
#define QSCALE 0.18033688011112042f
// l1 compensation: |s_nat| = |s_log2| * ln2
#define L1SCALE (0.6931471805599453f / 33554432.0f)   // ln2 / (8*2048*2048)

// ---------------- scratch (device globals; no allocations allowed) ----------
__device__ __nv_bfloat16 g_qh[(size_t)BATCH*NHEADS*SEQ*EMB];
__device__ __nv_bfloat16 g_ql[(size_t)BATCH*NHEADS*SEQ*EMB];
__device__ __nv_bfloat16 g_kh[(size_t)BATCH*NHEADS*SEQ*EMB];
__device__ __nv_bfloat16 g_kl[(size_t)BATCH*NHEADS*SEQ*EMB];
__device__ __nv_bfloat16 g_vh[(size_t)BATCH*FB*SEQ];
__device__ __nv_bfloat16 g_vl[(size_t)BATCH*FB*SEQ];
__device__ __nv_bfloat16 g_wh[(size_t)FA*HFB];
__device__ __nv_bfloat16 g_wl[(size_t)FA*HFB];
__device__ __nv_bfloat16 g_fh[(size_t)BATCH*SEQ*HFB];
__device__ __nv_bfloat16 g_fl[(size_t)BATCH*SEQ*HFB];

// ============================ helpers ========================================
__device__ __forceinline__ uint32_t smem_u32(const void* p) {
    uint32_t a;
    asm("{ .reg .u64 t; cvta.to.shared.u64 t, %1; cvt.u32.u64 %0, t; }" : "=r"(a) : "l"(p));
    return a;
}
#define CP_ASYNC16(dst, src) \
    asm volatile("cp.async.cg.shared.global [%0], [%1], 16;" :: "r"(dst), "l"(src))
#define CP_COMMIT() asm volatile("cp.async.commit_group;" ::: "memory")
#define CP_WAIT(n)  asm volatile("cp.async.wait_group %0;" :: "n"(n) : "memory")

#define LDSM4(r, addr) \
    asm volatile("ldmatrix.sync.aligned.m8n8.x4.shared.b16 {%0,%1,%2,%3}, [%4];" \
        : "=r"((r)[0]), "=r"((r)[1]), "=r"((r)[2]), "=r"((r)[3]) : "r"(addr))

#define MMA16816(d, a, b0, b1)                                                  \
    asm volatile("mma.sync.aligned.m16n8k16.row.col.f32.bf16.bf16.f32 "         \
        "{%0,%1,%2,%3}, {%4,%5,%6,%7}, {%8,%9}, {%0,%1,%2,%3};"                 \
        : "+f"((d)[0]), "+f"((d)[1]), "+f"((d)[2]), "+f"((d)[3])                \
        : "r"((a)[0]), "r"((a)[1]), "r"((a)[2]), "r"((a)[3]), "r"(b0), "r"(b1))

__device__ __forceinline__ void cvt_hl(float v, __nv_bfloat16& h, __nv_bfloat16& l) {
    h = __float2bfloat16_rn(v);
    l = __float2bfloat16_rn(v - __bfloat162float(h));
}
__device__ __forceinline__ uint32_t pack2(__nv_bfloat16 a, __nv_bfloat16 b) {
    return ((uint32_t)__bfloat16_as_ushort(b) << 16) | (uint32_t)__bfloat16_as_ushort(a);
}
__device__ __forceinline__ float ex2(float x) {
    float y; asm("ex2.approx.f32 %0, %1;" : "=f"(y) : "f"(x)); return y;
}

// ---- tile stage format (proven): per 16-k slice a row is 64B:
// [hi: 2 x 16B chunks | lo: 2 x 16B chunks], chunk' = chunk ^ ((row>>1)&3).
template<int R, int NS, int NT>
__device__ __forceinline__ void issue_tile(uint32_t sb,
    const __nv_bfloat16* __restrict__ Gh, const __nv_bfloat16* __restrict__ Gl, int ld)
{
    const int tid = threadIdx.x;
    constexpr int CPT = (R * NS * 4) / NT;
    #pragma unroll
    for (int p = 0; p < CPT; p++) {
        int id  = tid + p * NT;
        int s   = id / (R * 4);
        int rem = id - s * (R * 4);
        int r   = rem >> 2, cc = rem & 3;
        const __nv_bfloat16* src = (cc < 2 ? Gh : Gl)
            + (size_t)r * ld + s * 16 + ((cc & 1) << 3);
        uint32_t dst = sb + s * (R * 64) + r * 64 + ((cc ^ ((r >> 1) & 3)) << 4);
        CP_ASYNC16(dst, src);
    }
}

// A frag, single 16-row m-frag (rows wm..wm+15)
__device__ __forceinline__ void lda_frag1(uint32_t stb, int wm, int lane,
                                          uint32_t ah[4], uint32_t al[4])
{
    int r  = wm + (lane & 15);
    int ch = (lane >> 4) & 1;
    uint32_t rb = stb + r * 64;
    LDSM4(ah, rb + (((ch)     ^ ((r >> 1) & 3)) << 4));
    LDSM4(al, rb + (((ch + 2) ^ ((r >> 1) & 3)) << 4));
}
// B frags, 32 rows (wn..wn+31)
__device__ __forceinline__ void ldb_frag(uint32_t stb, int wn, int lane,
                                         uint32_t bh_[2][4], uint32_t bl_[2][4])
{
    #pragma unroll
    for (int nb = 0; nb < 2; nb++) {
        int r  = wn + nb * 16 + (lane & 7) + ((lane & 16) ? 8 : 0);
        int ch = (lane >> 3) & 1;
        uint32_t rb = stb + r * 64;
        LDSM4(bh_[nb], rb + (((ch)     ^ ((r >> 1) & 3)) << 4));
        LDSM4(bl_[nb], rb + (((ch + 2) ^ ((r >> 1) & 3)) << 4));
    }
}

// ---------------- fused attention smem layout (dynamic) ----------------------
// Q: 128 rows x 4 stages = 32768 (persistent)
// K: 64 rows x 4 stages  = 16384 x2 (double buffer)
// V: 256 rows x 4 stages = 65536 x2 (double buffer)
#define OQ2   0
#define OK0   32768
#define OK1   49152
#define OV0b  65536
#define OV1b  131072
#define ORED2 196608
#define SMEM_F2 196672

// ============ fused: pre + softmax(+l1) + feat, per (bh, 128-q tile) =========
// 256 threads, 8 warps; warp w owns q-rows w*16..w*16+15 and ALL 256 f cols.
// P never touches smem: S C-fragments are re-packed in registers as PV A-frags.
__global__ __launch_bounds__(256, 1) void attn_fused_kernel(float* __restrict__ l1)
{
    extern __shared__ char SM[];
    const uint32_t SB = smem_u32(SM);
    const int tid = threadIdx.x, lane = tid & 31, wid = tid >> 5;
    const int wm = wid * 16;
    const int qt = blockIdx.x, bh = blockIdx.y;
    const int b = bh >> 3, h = bh & 7;
    const int qbase = qt * 128;
    float* red = (float*)(SM + ORED2);

    const __nv_bfloat16* Qh = g_qh + ((size_t)bh * SEQ + qbase) * EMB;
    const __nv_bfloat16* Ql = g_ql + ((size_t)bh * SEQ + qbase) * EMB;
    const __nv_bfloat16* Kh = g_kh + (size_t)bh * SEQ * EMB;
    const __nv_bfloat16* Kl = g_kl + (size_t)bh * SEQ * EMB;
    const __nv_bfloat16* Vh = g_vh + (size_t)b * FB * SEQ;
    const __nv_bfloat16* Vl = g_vl + (size_t)b * FB * SEQ;

    // prologue: Q (persistent) + chunk 0, one commit group
    issue_tile<128, 4, 256>(SB + OQ2, Qh, Ql, EMB);
    issue_tile<64, 4, 256>(SB + OK0, Kh, Kl, EMB);
    issue_tile<256, 4, 256>(SB + OV0b, Vh, Vl, SEQ);
    CP_COMMIT();

    float oacc[32][4] = {};     // 16 q-rows x 256 f per warp
    float l1acc = 0.0f;
    float rs0 = 0.0f, rs1 = 0.0f;   // running exp row sums (rows lane>>2, +8)

    for (int j = 0; j < 32; j++) {
        const int jn = (j + 1) & 31;
        CP_WAIT(0);              // chunk j resident
        __syncthreads();         // visible to all; prev buffer fully consumed

        // prefetch chunk j+1 into the other buffer (flies under compute)
        issue_tile<64, 4, 256>(SB + ((jn & 1) ? OK1 : OK0),
                               Kh + (size_t)jn * 64 * EMB,
                               Kl + (size_t)jn * 64 * EMB, EMB);
        issue_tile<256, 4, 256>(SB + ((jn & 1) ? OV1b : OV0b),
                                Vh + jn * 64, Vl + jn * 64, SEQ);
        CP_COMMIT();

        const uint32_t kb = SB + ((j & 1) ? OK1 : OK0);
        const uint32_t vb = SB + ((j & 1) ? OV1b : OV0b);

        // ---- S = Q x K^T (16 q x 64 keys, K=64), bf16x3, log2-domain ----
        float sacc[8][4] = {};
        #pragma unroll
        for (int es = 0; es < 4; es++) {
            uint32_t qh_[4], ql_[4];
            lda_frag1(SB + OQ2 + es * 8192, wm, lane, qh_, ql_);
            #pragma unroll
            for (int half = 0; half < 2; half++) {
                uint32_t kbh[2][4], kbl[2][4];
                ldb_frag(kb + es * 4096, half * 32, lane, kbh, kbl);
                #pragma unroll
                for (int ni = 0; ni < 4; ni++) {
                    const int g = ni >> 1, o = (ni & 1) << 1;
                    float* d = sacc[half * 4 + ni];
                    MMA16816(d, qh_, kbh[g][o], kbh[g][o + 1]);
                    MMA16816(d, qh_, kbl[g][o], kbl[g][o + 1]);
                    MMA16816(d, ql_, kbh[g][o], kbh[g][o + 1]);
                }
            }
        }

        // ---- per 16-key slice: convert S->P in registers, then PV ----
        #pragma unroll
        for (int kf = 0; kf < 4; kf++) {
            // convert sacc[2kf], sacc[2kf+1] -> PV A-fragment (hi/lo)
            uint32_t pAh[4], pAl[4];
            {
                const float* s0 = sacc[2 * kf];
                const float* s1 = sacc[2 * kf + 1];
                l1acc += fabsf(s0[0]) + fabsf(s0[1]) + fabsf(s0[2]) + fabsf(s0[3])
                       + fabsf(s1[0]) + fabsf(s1[1]) + fabsf(s1[2]) + fabsf(s1[3]);
                float p00 = ex2(s0[0]), p01 = ex2(s0[1]), p02 = ex2(s0[2]), p03 = ex2(s0[3]);
                float p10 = ex2(s1[0]), p11 = ex2(s1[1]), p12 = ex2(s1[2]), p13 = ex2(s1[3]);
                rs0 += p00 + p01 + p10 + p11;
                rs1 += p02 + p03 + p12 + p13;
                __nv_bfloat16 H0, L0, H1, L1;
                cvt_hl(p00, H0, L0); cvt_hl(p01, H1, L1);
                pAh[0] = pack2(H0, H1); pAl[0] = pack2(L0, L1);
                cvt_hl(p02, H0, L0); cvt_hl(p03, H1, L1);
                pAh[1] = pack2(H0, H1); pAl[1] = pack2(L0, L1);
                cvt_hl(p10, H0, L0); cvt_hl(p11, H1, L1);
                pAh[2] = pack2(H0, H1); pAl[2] = pack2(L0, L1);
                cvt_hl(p12, H0, L0); cvt_hl(p13, H1, L1);
                pAh[3] = pack2(H0, H1); pAl[3] = pack2(L0, L1);
            }
            // PV: O[16q x 256f] += P_slice x V_slice^T
            #pragma unroll
            for (int c8 = 0; c8 < 8; c8++) {
                uint32_t vh_[2][4], vl_[2][4];
                ldb_frag(vb + kf * 16384, c8 * 32, lane, vh_, vl_);
                #pragma unroll
                for (int ni = 0; ni < 4; ni++) {
                    const int g = ni >> 1, o = (ni & 1) << 1;
                    float* d = oacc[c8 * 4 + ni];
                    MMA16816(d, pAh, vh_[g][o], vh_[g][o + 1]);
                    MMA16816(d, pAh, vl_[g][o], vl_[g][o + 1]);
                    MMA16816(d, pAl, vh_[g][o], vh_[g][o + 1]);
                }
            }
        }
    }

    CP_WAIT(0);

    // ---- epilogue: reduce row sums, normalize, write feat hi/lo ----
    rs0 += __shfl_xor_sync(0xffffffffu, rs0, 1);
    rs0 += __shfl_xor_sync(0xffffffffu, rs0, 2);
    rs1 += __shfl_xor_sync(0xffffffffu, rs1, 1);
    rs1 += __shfl_xor_sync(0xffffffffu, rs1, 2);
    const float inv0 = 1.0f / rs0;
    const float inv1 = 1.0f / rs1;

    const int r0 = qbase + wm + (lane >> 2);
    const size_t row0 = ((size_t)b * SEQ + r0) * HFB + h * FB;
    const size_t row1 = ((size_t)b * SEQ + r0 + 8) * HFB + h * FB;
    #pragma unroll
    for (int nf = 0; nf < 32; nf++) {
        const float* a = oacc[nf];
        const int c = nf * 8 + ((lane & 3) << 1);
        float v0 = a[0] * inv0, v1 = a[1] * inv0;
        float v2 = a[2] * inv1, v3 = a[3] * inv1;
        __nv_bfloat16 H0, L0, H1, L1;
        cvt_hl(v0, H0, L0); cvt_hl(v1, H1, L1);
        *(uint32_t*)(g_fh + row0 + c) = pack2(H0, H1);
        *(uint32_t*)(g_fl + row0 + c) = pack2(L0, L1);
        cvt_hl(v2, H0, L0); cvt_hl(v3, H1, L1);
        *(uint32_t*)(g_fh + row1 + c) = pack2(H0, H1);
        *(uint32_t*)(g_fl + row1 + c) = pack2(L0, L1);
    }

    // ---- l1 reduction (log2-domain sums, scaled by ln2) ----
    #pragma unroll
    for (int o = 16; o > 0; o >>= 1)
        l1acc += __shfl_xor_sync(0xffffffffu, l1acc, o);
    if (lane == 0) red[wid] = l1acc;
    __syncthreads();
    if (tid == 0) {
        float t = 0.0f;
        #pragma unroll
        for (int w = 0; w < 8; w++) t += red[w];
        atomicAdd(&l1[b], t * L1SCALE);
    }
}

// ---------------- tiny init --------------------------------------------------
__global__ void zero_l1_kernel(float* l1) {
    if (threadIdx.x < BATCH) l1[threadIdx.x] = 0.0f;
}

// ---------------- conv: z_b and W_c -> bf16 hi/lo ----------------------------
__global__ __launch_bounds__(256) void conv_kernel(const float* __restrict__ zb,
                                                   const float* __restrict__ Wc)
{
    const int NZ = BATCH * FB * SEQ / 4;
    const int NW = FA * HFB / 4;
    int i = blockIdx.x * 256 + threadIdx.x;
    if (i < NZ) {
        float4 v = ((const float4*)zb)[i];
        __nv_bfloat16 h0,l0,h1,l1,h2,l2,h3,l3;
        cvt_hl(v.x,h0,l0); cvt_hl(v.y,h1,l1); cvt_hl(v.z,h2,l2); cvt_hl(v.w,h3,l3);
        ((uint2*)g_vh)[i] = make_uint2(pack2(h0,h1), pack2(h2,h3));
        ((uint2*)g_vl)[i] = make_uint2(pack2(l0,l1), pack2(l2,l3));
    } else if (i < NZ + NW) {
        int j = i - NZ;
        float4 v = ((const float4*)Wc)[j];
        __nv_bfloat16 h0,l0,h1,l1,h2,l2,h3,l3;
        cvt_hl(v.x,h0,l0); cvt_hl(v.y,h1,l1); cvt_hl(v.z,h2,l2); cvt_hl(v.w,h3,l3);
        ((uint2*)g_wh)[j] = make_uint2(pack2(h0,h1), pack2(h2,h3));
        ((uint2*)g_wl)[j] = make_uint2(pack2(l0,l1), pack2(l2,l3));
    }
}

// ---------------- embed: fp32 SIMT GEMM, epilogue -> qT/kT bf16 hi/lo --------
#define BM 128
#define BN 128
#define BK 8
#define TM 8
#define TN 8
__global__ __launch_bounds__(256) void embed_kernel(
    const float* __restrict__ Wa, const float* __restrict__ za,
    const float* __restrict__ Wb, const float* __restrict__ zb)
{
    const int bz = blockIdx.z;
    const int b = bz >> 1, sel = bz & 1;
    const float* __restrict__ A  = sel ? Wb : Wa;                       // [512 x 256]
    const float* __restrict__ Bm = (sel ? zb : za) + (size_t)b*FA*SEQ;  // [256 x 2048]
    __nv_bfloat16* __restrict__ Oh = sel ? g_kh : g_qh;
    __nv_bfloat16* __restrict__ Ol = sel ? g_kl : g_ql;
    const float scl = sel ? 1.0f : QSCALE;

    __shared__ float As[BK][BM];
    __shared__ float Bs[BK][BN];

    const int tid = threadIdx.x;
    const int m0 = blockIdx.y * BM;
    const int n0 = blockIdx.x * BN;
    const int K = FA;
    const int ty = tid >> 4, tx = tid & 15;

    float acc[TM][TN] = {};

    for (int k0 = 0; k0 < K; k0 += BK) {
        {
            const int mm = tid >> 1, kk = (tid & 1) * 4;
            float4 v = *(const float4*)&A[(size_t)(m0 + mm) * K + k0 + kk];
            As[kk + 0][mm] = v.x; As[kk + 1][mm] = v.y;
            As[kk + 2][mm] = v.z; As[kk + 3][mm] = v.w;
        }
        {
            const int kk = tid >> 5, nn = (tid & 31) * 4;
            *(float4*)&Bs[kk][nn] = *(const float4*)&Bm[(size_t)(k0 + kk) * SEQ + n0 + nn];
        }
        __syncthreads();
        #pragma unroll
        for (int kk = 0; kk < BK; kk++) {
            float a[TM], bb[TN];
            *(float4*)&a[0]  = *(const float4*)&As[kk][ty * TM];
            *(float4*)&a[4]  = *(const float4*)&As[kk][ty * TM + 4];
            *(float4*)&bb[0] = *(const float4*)&Bs[kk][tx * TN];
            *(float4*)&bb[4] = *(const float4*)&Bs[kk][tx * TN + 4];
            #pragma unroll
            for (int i = 0; i < TM; i++)
                #pragma unroll
                for (int j = 0; j < TN; j++)
                    acc[i][j] += a[i] * bb[j];
        }
        __syncthreads();
    }
    // transposed epilogue: m = o = h*64+e -> write [bh][n][e]
    const int mbase = m0 + ty * TM;
    const int h = mbase >> 6, e0 = mbase & 63;
    const size_t bh = (size_t)(b * NHEADS + h);
    #pragma unroll
    for (int j = 0; j < TN; j++) {
        const int n = n0 + tx * TN + j;
        uint32_t hw[4], lw[4];
        #pragma unroll
        for (int p = 0; p < 4; p++) {
            __nv_bfloat16 ha, la, hb, lb;
            cvt_hl(acc[2*p][j] * scl, ha, la);
            cvt_hl(acc[2*p+1][j] * scl, hb, lb);
            hw[p] = pack2(ha, hb); lw[p] = pack2(la, lb);
        }
        const size_t dst = (bh * SEQ + n) * EMB + e0;
        *(uint4*)(Oh + dst) = make_uint4(hw[0], hw[1], hw[2], hw[3]);
        *(uint4*)(Ol + dst) = make_uint4(lw[0], lw[1], lw[2], lw[3]);
    }
}

// ---------------- out: mma.sync bf16x3, K=2048, fp32 out ---------------------
#define ISSUE_STAGE(st, k0)                                                     \
    do {                                                                        \
        _Pragma("unroll")                                                       \
        for (int p = 0; p < 4; p++) {                                           \
            int id = tid + (p << 8);                                            \
            int isB = id >> 9;                                                  \
            int rem = id & 511;                                                 \
            int r = rem >> 2, cc = rem & 3;                                     \
            const __nv_bfloat16* src =                                          \
                (isB ? (cc < 2 ? Bh : Bl) : (cc < 2 ? Ah : Al))                 \
                + (size_t)r * (isB ? ldb : lda) + (k0) + ((cc & 1) << 3);       \
            uint32_t dst = sb + (st) * 16384 + isB * 8192 + r * 64              \
                         + ((cc ^ ((r >> 1) & 3)) << 4);                        \
            CP_ASYNC16(dst, src);                                               \
        }                                                                       \
    } while (0)

__device__ __forceinline__ void mma_nt_128(
    const __nv_bfloat16* __restrict__ Ah, const __nv_bfloat16* __restrict__ Al, int lda,
    const __nv_bfloat16* __restrict__ Bh, const __nv_bfloat16* __restrict__ Bl, int ldb,
    int K, float acc[4][4][4], unsigned char* sbuf)
{
    const int tid  = threadIdx.x;
    const int lane = tid & 31;
    const int wid  = tid >> 5;
    const int wm   = (wid >> 2) * 64;
    const int wn   = (wid & 3) * 32;
    const uint32_t sb = smem_u32(sbuf);

    #pragma unroll
    for (int mi = 0; mi < 4; mi++)
        #pragma unroll
        for (int ni = 0; ni < 4; ni++)
            #pragma unroll
            for (int q = 0; q < 4; q++) acc[mi][ni][q] = 0.0f;

    const int nst = K >> 4;
    ISSUE_STAGE(0, 0);
    CP_COMMIT();

    for (int s = 0; s < nst; s++) {
        if (s + 1 < nst) {
            ISSUE_STAGE((s + 1) & 1, (s + 1) << 4);
            CP_COMMIT();
            CP_WAIT(1);
        } else {
            CP_WAIT(0);
        }
        __syncthreads();

        const uint32_t stb = sb + (uint32_t)(s & 1) * 16384;
        uint32_t ah[4][4], al[4][4], bhf[2][4], blf[2][4];
        #pragma unroll
        for (int mi = 0; mi < 4; mi++) {
            int r  = wm + mi * 16 + (lane & 15);
            int ch = (lane >> 4) & 1;
            uint32_t rb = stb + r * 64;
            LDSM4(ah[mi], rb + (((ch)     ^ ((r >> 1) & 3)) << 4));
            LDSM4(al[mi], rb + (((ch + 2) ^ ((r >> 1) & 3)) << 4));
        }
        #pragma unroll
        for (int nb = 0; nb < 2; nb++) {
            int r  = wn + nb * 16 + (lane & 7) + ((lane & 16) ? 8 : 0);
            int ch = (lane >> 3) & 1;
            uint32_t rb = stb + 8192 + r * 64;
            LDSM4(bhf[nb], rb + (((ch)     ^ ((r >> 1) & 3)) << 4));
            LDSM4(blf[nb], rb + (((ch + 2) ^ ((r >> 1) & 3)) << 4));
        }
        #pragma unroll
        for (int mi = 0; mi < 4; mi++)
            #pragma unroll
            for (int ni = 0; ni < 4; ni++) {
                const int g = ni >> 1, o = (ni & 1) << 1;
                MMA16816(acc[mi][ni], ah[mi], bhf[g][o], bhf[g][o + 1]);
                MMA16816(acc[mi][ni], ah[mi], blf[g][o], blf[g][o + 1]);
                MMA16816(acc[mi][ni], al[mi], bhf[g][o], bhf[g][o + 1]);
            }
        __syncthreads();
    }
}

__global__ __launch_bounds__(256) void out_mma_kernel(float* __restrict__ out)
{
    __shared__ __align__(16) unsigned char sbuf[2][16384];
    const int tid = threadIdx.x, lane = tid & 31, wid = tid >> 5;
    const int b = blockIdx.z;
    const int m0 = blockIdx.y * 128;
    const int n0 = blockIdx.x * 128;

    const __nv_bfloat16* Ah = g_fh + ((size_t)b * SEQ + m0) * HFB;
    const __nv_bfloat16* Al = g_fl + ((size_t)b * SEQ + m0) * HFB;
    const __nv_bfloat16* Bh = g_wh + (size_t)n0 * HFB;
    const __nv_bfloat16* Bl = g_wl + (size_t)n0 * HFB;

    float acc[4][4][4];
    mma_nt_128(Ah, Al, HFB, Bh, Bl, HFB, HFB, acc, &sbuf[0][0]);

    const int wm = (wid >> 2) * 64, wn = (wid & 3) * 32;
    #pragma unroll
    for (int mi = 0; mi < 4; mi++) {
        #pragma unroll
        for (int ni = 0; ni < 4; ni++) {
            const int r0 = m0 + wm + mi * 16 + (lane >> 2);
            const int c  = n0 + wn + ni * 8 + ((lane & 3) << 1);
            *(float2*)(out + ((size_t)b * SEQ + r0) * FA + c) =
                make_float2(acc[mi][ni][0], acc[mi][ni][1]);
            *(float2*)(out + ((size_t)b * SEQ + r0 + 8) * FA + c) =
                make_float2(acc[mi][ni][2], acc[mi][ni][3]);
        }
    }
}

// ---------------- launch -----------------------------------------------------
extern "C" void kernel_launch(void* const* d_in, const int* in_sizes, int n_in,
                              void* d_out, int out_size)
{
    const float* z_a = (const float*)d_in[0];   // [2, 256, 2048]
    const float* z_b = (const float*)d_in[1];   // [2, 256, 2048]
    const float* W_a = (const float*)d_in[2];   // [512, 256]
    const float* W_b = (const float*)d_in[3];   // [512, 256]
    const float* W_c = (const float*)d_in[4];   // [256, 2048]
    float* out = (float*)d_out;                 // [2, 2048, 256] then l1 [2]
    float* l1  = out + (size_t)BATCH * SEQ * FA;

    cudaFuncSetAttribute(attn_fused_kernel,
                         cudaFuncAttributeMaxDynamicSharedMemorySize, SMEM_F2);

    zero_l1_kernel<<<1, 32>>>(l1);

    {
        const int nchunks = (BATCH * FB * SEQ + FA * HFB) / 4;
        conv_kernel<<<(nchunks + 255) / 256, 256>>>(z_b, W_c);
    }
    {
        dim3 grid(SEQ / BN, (NHEADS * EMB) / BM, BATCH * 2);
        embed_kernel<<<grid, 256>>>(W_a, z_a, W_b, z_b);
    }
    {
        dim3 grid(SEQ / 128, BATCH * NHEADS);
        attn_fused_kernel<<<grid, 256, SMEM_F2>>>(l1);
    }
    {
        dim3 grid(FA / 128, SEQ / 128, BATCH);
        out_mma_kernel<<<grid, 256>>>(out);
    }
}

// round 16
// speedup vs baseline: 1.3236x; 1.0478x over previous
#include <cuda_runtime.h>
#include <cuda_bf16.h>
#include <math.h>
#include <stdint.h>

#define NHEADS 8
#define EMB    64
#define FA     256
#define FB     256
#define BATCH  2
#define SEQ    2048
#define HFB    (NHEADS*FB)   // 2048

#define QSCALE 0.18033688011112042f
#define L1SCALE (0.6931471805599453f / 33554432.0f)   // ln2 / (8*2048*2048)

// ---------------- scratch (device globals; no allocations allowed) ----------
__device__ __nv_bfloat16 g_qh[(size_t)BATCH*NHEADS*SEQ*EMB];
__device__ __nv_bfloat16 g_ql[(size_t)BATCH*NHEADS*SEQ*EMB];
__device__ __nv_bfloat16 g_kh[(size_t)BATCH*NHEADS*SEQ*EMB];
__device__ __nv_bfloat16 g_kl[(size_t)BATCH*NHEADS*SEQ*EMB];
__device__ __nv_bfloat16 g_vh[(size_t)BATCH*FB*SEQ];
__device__ __nv_bfloat16 g_vl[(size_t)BATCH*FB*SEQ];
__device__ __nv_bfloat16 g_wh[(size_t)FA*HFB];
__device__ __nv_bfloat16 g_wl[(size_t)FA*HFB];
__device__ __nv_bfloat16 g_fh[(size_t)BATCH*SEQ*HFB];
__device__ __nv_bfloat16 g_fl[(size_t)BATCH*SEQ*HFB];

// ============================ helpers ========================================
__device__ __forceinline__ uint32_t smem_u32(const void* p) {
    uint32_t a;
    asm("{ .reg .u64 t; cvta.to.shared.u64 t, %1; cvt.u32.u64 %0, t; }" : "=r"(a) : "l"(p));
    return a;
}
#define CP_ASYNC16(dst, src) \
    asm volatile("cp.async.cg.shared.global [%0], [%1], 16;" :: "r"(dst), "l"(src))
#define CP_COMMIT() asm volatile("cp.async.commit_group;" ::: "memory")
#define CP_WAIT(n)  asm volatile("cp.async.wait_group %0;" :: "n"(n) : "memory")

#define LDSM4(r, addr) \
    asm volatile("ldmatrix.sync.aligned.m8n8.x4.shared.b16 {%0,%1,%2,%3}, [%4];" \
        : "=r"((r)[0]), "=r"((r)[1]), "=r"((r)[2]), "=r"((r)[3]) : "r"(addr))

#define MMA16816(d, a, b0, b1)                                                  \
    asm volatile("mma.sync.aligned.m16n8k16.row.col.f32.bf16.bf16.f32 "         \
        "{%0,%1,%2,%3}, {%4,%5,%6,%7}, {%8,%9}, {%0,%1,%2,%3};"                 \
        : "+f"((d)[0]), "+f"((d)[1]), "+f"((d)[2]), "+f"((d)[3])                \
        : "r"((a)[0]), "r"((a)[1]), "r"((a)[2]), "r"((a)[3]), "r"(b0), "r"(b1))

__device__ __forceinline__ void cvt_hl(float v, __nv_bfloat16& h, __nv_bfloat16& l) {
    h = __float2bfloat16_rn(v);
    l = __float2bfloat16_rn(v - __bfloat162float(h));
}
__device__ __forceinline__ uint32_t pack2(__nv_bfloat16 a, __nv_bfloat16 b) {
    return ((uint32_t)__bfloat16_as_ushort(b) << 16) | (uint32_t)__bfloat16_as_ushort(a);
}
__device__ __forceinline__ float ex2(float x) {
    float y; asm("ex2.approx.f32 %0, %1;" : "=f"(y) : "f"(x)); return y;
}

// ---- tile stage format (proven): per 16-k slice a row is 64B:
// [hi: 2 x 16B chunks | lo: 2 x 16B chunks], chunk' = chunk ^ ((row>>1)&3).
template<int R, int NS, int NT>
__device__ __forceinline__ void issue_tile(uint32_t sb,
    const __nv_bfloat16* __restrict__ Gh, const __nv_bfloat16* __restrict__ Gl, int ld)
{
    const int tid = threadIdx.x;
    constexpr int CPT = (R * NS * 4) / NT;
    #pragma unroll
    for (int p = 0; p < CPT; p++) {
        int id  = tid + p * NT;
        int s   = id / (R * 4);
        int rem = id - s * (R * 4);
        int r   = rem >> 2, cc = rem & 3;
        const __nv_bfloat16* src = (cc < 2 ? Gh : Gl)
            + (size_t)r * ld + s * 16 + ((cc & 1) << 3);
        uint32_t dst = sb + s * (R * 64) + r * 64 + ((cc ^ ((r >> 1) & 3)) << 4);
        CP_ASYNC16(dst, src);
    }
}

// A frag, single 16-row m-frag (rows wm..wm+15)
__device__ __forceinline__ void lda_frag1(uint32_t stb, int wm, int lane,
                                          uint32_t ah[4], uint32_t al[4])
{
    int r  = wm + (lane & 15);
    int ch = (lane >> 4) & 1;
    uint32_t rb = stb + r * 64;
    LDSM4(ah, rb + (((ch)     ^ ((r >> 1) & 3)) << 4));
    LDSM4(al, rb + (((ch + 2) ^ ((r >> 1) & 3)) << 4));
}
// B frags, 32 rows (wn..wn+31)
__device__ __forceinline__ void ldb_frag(uint32_t stb, int wn, int lane,
                                         uint32_t bh_[2][4], uint32_t bl_[2][4])
{
    #pragma unroll
    for (int nb = 0; nb < 2; nb++) {
        int r  = wn + nb * 16 + (lane & 7) + ((lane & 16) ? 8 : 0);
        int ch = (lane >> 3) & 1;
        uint32_t rb = stb + r * 64;
        LDSM4(bh_[nb], rb + (((ch)     ^ ((r >> 1) & 3)) << 4));
        LDSM4(bl_[nb], rb + (((ch + 2) ^ ((r >> 1) & 3)) << 4));
    }
}

// ---------------- fused attention smem layout (dynamic) ----------------------
#define OQ2   0          // Q: 128 rows x 4 stages = 32768 (persistent)
#define OK0   32768      // K: 64 rows x 4 stages = 16384 x2
#define OK1   49152
#define OV0b  65536      // V: 256 rows x 4 stages = 65536 x2
#define OV1b  131072
#define ORED2 196608
#define SMEM_F2 196672

// ============ fused: pre + softmax(+l1) + feat, per (bh, 128-q tile) =========
// 256 threads, 8 warps; warp w owns q-rows w*16..w*16+15 and ALL 256 f cols.
// P never touches smem. 64-key chunks processed as 2x32-key halves (reg relief).
__global__ __launch_bounds__(256, 1) void attn_fused_kernel(float* __restrict__ l1)
{
    extern __shared__ char SM[];
    const uint32_t SB = smem_u32(SM);
    const int tid = threadIdx.x, lane = tid & 31, wid = tid >> 5;
    const int wm = wid * 16;
    const int qt = blockIdx.x, bh = blockIdx.y;
    const int b = bh >> 3, h = bh & 7;
    const int qbase = qt * 128;
    float* red = (float*)(SM + ORED2);

    const __nv_bfloat16* Qh = g_qh + ((size_t)bh * SEQ + qbase) * EMB;
    const __nv_bfloat16* Ql = g_ql + ((size_t)bh * SEQ + qbase) * EMB;
    const __nv_bfloat16* Kh = g_kh + (size_t)bh * SEQ * EMB;
    const __nv_bfloat16* Kl = g_kl + (size_t)bh * SEQ * EMB;
    const __nv_bfloat16* Vh = g_vh + (size_t)b * FB * SEQ;
    const __nv_bfloat16* Vl = g_vl + (size_t)b * FB * SEQ;

    issue_tile<128, 4, 256>(SB + OQ2, Qh, Ql, EMB);
    issue_tile<64, 4, 256>(SB + OK0, Kh, Kl, EMB);
    issue_tile<256, 4, 256>(SB + OV0b, Vh, Vl, SEQ);
    CP_COMMIT();

    float oacc[32][4] = {};     // 16 q-rows x 256 f per warp
    float l1acc = 0.0f;
    float rs0 = 0.0f, rs1 = 0.0f;

    for (int j = 0; j < 32; j++) {
        const int jn = (j + 1) & 31;
        CP_WAIT(0);
        __syncthreads();

        issue_tile<64, 4, 256>(SB + ((jn & 1) ? OK1 : OK0),
                               Kh + (size_t)jn * 64 * EMB,
                               Kl + (size_t)jn * 64 * EMB, EMB);
        issue_tile<256, 4, 256>(SB + ((jn & 1) ? OV1b : OV0b),
                                Vh + jn * 64, Vl + jn * 64, SEQ);
        CP_COMMIT();

        const uint32_t kb = SB + ((j & 1) ? OK1 : OK0);
        const uint32_t vb = SB + ((j & 1) ? OV1b : OV0b);

        // ---- process 64-key chunk as 2 x 32-key halves (identical order) ----
        #pragma unroll
        for (int half = 0; half < 2; half++) {
            // S = Q x K_half^T (16 q x 32 keys, K=64)
            float sacc[4][4] = {};
            #pragma unroll
            for (int es = 0; es < 4; es++) {
                uint32_t qh_[4], ql_[4], kbh[2][4], kbl[2][4];
                lda_frag1(SB + OQ2 + es * 8192, wm, lane, qh_, ql_);
                ldb_frag(kb + es * 4096, half * 32, lane, kbh, kbl);
                #pragma unroll
                for (int ni = 0; ni < 4; ni++) {
                    const int g = ni >> 1, o = (ni & 1) << 1;
                    MMA16816(sacc[ni], qh_, kbh[g][o], kbh[g][o + 1]);
                    MMA16816(sacc[ni], qh_, kbl[g][o], kbl[g][o + 1]);
                    MMA16816(sacc[ni], ql_, kbh[g][o], kbh[g][o + 1]);
                }
            }
            // per 16-key slice: convert S->P in registers, then PV
            #pragma unroll
            for (int kf = 0; kf < 2; kf++) {
                uint32_t pAh[4], pAl[4];
                {
                    const float* s0 = sacc[2 * kf];
                    const float* s1 = sacc[2 * kf + 1];
                    l1acc += fabsf(s0[0]) + fabsf(s0[1]) + fabsf(s0[2]) + fabsf(s0[3])
                           + fabsf(s1[0]) + fabsf(s1[1]) + fabsf(s1[2]) + fabsf(s1[3]);
                    float p00 = ex2(s0[0]), p01 = ex2(s0[1]), p02 = ex2(s0[2]), p03 = ex2(s0[3]);
                    float p10 = ex2(s1[0]), p11 = ex2(s1[1]), p12 = ex2(s1[2]), p13 = ex2(s1[3]);
                    rs0 += p00 + p01 + p10 + p11;
                    rs1 += p02 + p03 + p12 + p13;
                    __nv_bfloat16 H0, L0, H1, L1;
                    cvt_hl(p00, H0, L0); cvt_hl(p01, H1, L1);
                    pAh[0] = pack2(H0, H1); pAl[0] = pack2(L0, L1);
                    cvt_hl(p02, H0, L0); cvt_hl(p03, H1, L1);
                    pAh[1] = pack2(H0, H1); pAl[1] = pack2(L0, L1);
                    cvt_hl(p10, H0, L0); cvt_hl(p11, H1, L1);
                    pAh[2] = pack2(H0, H1); pAl[2] = pack2(L0, L1);
                    cvt_hl(p12, H0, L0); cvt_hl(p13, H1, L1);
                    pAh[3] = pack2(H0, H1); pAl[3] = pack2(L0, L1);
                }
                const uint32_t vslice = vb + (half * 2 + kf) * 16384;
                #pragma unroll
                for (int c8 = 0; c8 < 8; c8++) {
                    uint32_t vh_[2][4], vl_[2][4];
                    ldb_frag(vslice, c8 * 32, lane, vh_, vl_);
                    #pragma unroll
                    for (int ni = 0; ni < 4; ni++) {
                        const int g = ni >> 1, o = (ni & 1) << 1;
                        float* d = oacc[c8 * 4 + ni];
                        MMA16816(d, pAh, vh_[g][o], vh_[g][o + 1]);
                        MMA16816(d, pAh, vl_[g][o], vl_[g][o + 1]);
                        MMA16816(d, pAl, vh_[g][o], vh_[g][o + 1]);
                    }
                }
            }
        }
    }

    CP_WAIT(0);

    // ---- epilogue: reduce row sums, normalize, write feat hi/lo ----
    rs0 += __shfl_xor_sync(0xffffffffu, rs0, 1);
    rs0 += __shfl_xor_sync(0xffffffffu, rs0, 2);
    rs1 += __shfl_xor_sync(0xffffffffu, rs1, 1);
    rs1 += __shfl_xor_sync(0xffffffffu, rs1, 2);
    const float inv0 = 1.0f / rs0;
    const float inv1 = 1.0f / rs1;

    const int r0 = qbase + wm + (lane >> 2);
    const size_t row0 = ((size_t)b * SEQ + r0) * HFB + h * FB;
    const size_t row1 = ((size_t)b * SEQ + r0 + 8) * HFB + h * FB;
    #pragma unroll
    for (int nf = 0; nf < 32; nf++) {
        const float* a = oacc[nf];
        const int c = nf * 8 + ((lane & 3) << 1);
        float v0 = a[0] * inv0, v1 = a[1] * inv0;
        float v2 = a[2] * inv1, v3 = a[3] * inv1;
        __nv_bfloat16 H0, L0, H1, L1;
        cvt_hl(v0, H0, L0); cvt_hl(v1, H1, L1);
        *(uint32_t*)(g_fh + row0 + c) = pack2(H0, H1);
        *(uint32_t*)(g_fl + row0 + c) = pack2(L0, L1);
        cvt_hl(v2, H0, L0); cvt_hl(v3, H1, L1);
        *(uint32_t*)(g_fh + row1 + c) = pack2(H0, H1);
        *(uint32_t*)(g_fl + row1 + c) = pack2(L0, L1);
    }

    #pragma unroll
    for (int o = 16; o > 0; o >>= 1)
        l1acc += __shfl_xor_sync(0xffffffffu, l1acc, o);
    if (lane == 0) red[wid] = l1acc;
    __syncthreads();
    if (tid == 0) {
        float t = 0.0f;
        #pragma unroll
        for (int w = 0; w < 8; w++) t += red[w];
        atomicAdd(&l1[b], t * L1SCALE);
    }
}

// ---------------- tiny init --------------------------------------------------
__global__ void zero_l1_kernel(float* l1) {
    if (threadIdx.x < BATCH) l1[threadIdx.x] = 0.0f;
}

// ---------------- conv: z_b and W_c -> bf16 hi/lo ----------------------------
__global__ __launch_bounds__(256) void conv_kernel(const float* __restrict__ zb,
                                                   const float* __restrict__ Wc)
{
    const int NZ = BATCH * FB * SEQ / 4;
    const int NW = FA * HFB / 4;
    int i = blockIdx.x * 256 + threadIdx.x;
    if (i < NZ) {
        float4 v = ((const float4*)zb)[i];
        __nv_bfloat16 h0,l0,h1,l1,h2,l2,h3,l3;
        cvt_hl(v.x,h0,l0); cvt_hl(v.y,h1,l1); cvt_hl(v.z,h2,l2); cvt_hl(v.w,h3,l3);
        ((uint2*)g_vh)[i] = make_uint2(pack2(h0,h1), pack2(h2,h3));
        ((uint2*)g_vl)[i] = make_uint2(pack2(l0,l1), pack2(l2,l3));
    } else if (i < NZ + NW) {
        int j = i - NZ;
        float4 v = ((const float4*)Wc)[j];
        __nv_bfloat16 h0,l0,h1,l1,h2,l2,h3,l3;
        cvt_hl(v.x,h0,l0); cvt_hl(v.y,h1,l1); cvt_hl(v.z,h2,l2); cvt_hl(v.w,h3,l3);
        ((uint2*)g_wh)[j] = make_uint2(pack2(h0,h1), pack2(h2,h3));
        ((uint2*)g_wl)[j] = make_uint2(pack2(l0,l1), pack2(l2,l3));
    }
}

// ---------------- embed: fp32 SIMT GEMM, epilogue -> qT/kT bf16 hi/lo --------
#define BM 128
#define BN 128
#define BK 8
#define TM 8
#define TN 8
__global__ __launch_bounds__(256) void embed_kernel(
    const float* __restrict__ Wa, const float* __restrict__ za,
    const float* __restrict__ Wb, const float* __restrict__ zb)
{
    const int bz = blockIdx.z;
    const int b = bz >> 1, sel = bz & 1;
    const float* __restrict__ A  = sel ? Wb : Wa;
    const float* __restrict__ Bm = (sel ? zb : za) + (size_t)b*FA*SEQ;
    __nv_bfloat16* __restrict__ Oh = sel ? g_kh : g_qh;
    __nv_bfloat16* __restrict__ Ol = sel ? g_kl : g_ql;
    const float scl = sel ? 1.0f : QSCALE;

    __shared__ float As[BK][BM];
    __shared__ float Bs[BK][BN];

    const int tid = threadIdx.x;
    const int m0 = blockIdx.y * BM;
    const int n0 = blockIdx.x * BN;
    const int K = FA;
    const int ty = tid >> 4, tx = tid & 15;

    float acc[TM][TN] = {};

    for (int k0 = 0; k0 < K; k0 += BK) {
        {
            const int mm = tid >> 1, kk = (tid & 1) * 4;
            float4 v = *(const float4*)&A[(size_t)(m0 + mm) * K + k0 + kk];
            As[kk + 0][mm] = v.x; As[kk + 1][mm] = v.y;
            As[kk + 2][mm] = v.z; As[kk + 3][mm] = v.w;
        }
        {
            const int kk = tid >> 5, nn = (tid & 31) * 4;
            *(float4*)&Bs[kk][nn] = *(const float4*)&Bm[(size_t)(k0 + kk) * SEQ + n0 + nn];
        }
        __syncthreads();
        #pragma unroll
        for (int kk = 0; kk < BK; kk++) {
            float a[TM], bb[TN];
            *(float4*)&a[0]  = *(const float4*)&As[kk][ty * TM];
            *(float4*)&a[4]  = *(const float4*)&As[kk][ty * TM + 4];
            *(float4*)&bb[0] = *(const float4*)&Bs[kk][tx * TN];
            *(float4*)&bb[4] = *(const float4*)&Bs[kk][tx * TN + 4];
            #pragma unroll
            for (int i = 0; i < TM; i++)
                #pragma unroll
                for (int j = 0; j < TN; j++)
                    acc[i][j] += a[i] * bb[j];
        }
        __syncthreads();
    }
    const int mbase = m0 + ty * TM;
    const int h = mbase >> 6, e0 = mbase & 63;
    const size_t bh = (size_t)(b * NHEADS + h);
    #pragma unroll
    for (int j = 0; j < TN; j++) {
        const int n = n0 + tx * TN + j;
        uint32_t hw[4], lw[4];
        #pragma unroll
        for (int p = 0; p < 4; p++) {
            __nv_bfloat16 ha, la, hb, lb;
            cvt_hl(acc[2*p][j] * scl, ha, la);
            cvt_hl(acc[2*p+1][j] * scl, hb, lb);
            hw[p] = pack2(ha, hb); lw[p] = pack2(la, lb);
        }
        const size_t dst = (bh * SEQ + n) * EMB + e0;
        *(uint4*)(Oh + dst) = make_uint4(hw[0], hw[1], hw[2], hw[3]);
        *(uint4*)(Ol + dst) = make_uint4(lw[0], lw[1], lw[2], lw[3]);
    }
}

// ---------------- out: mma.sync bf16x3, 64x128 tiles, K=2048, fp32 out -------
// stage: A 64 rows @0 (4096B), B 128 rows @4096 (8192B); stage stride 12288.
__global__ __launch_bounds__(256) void out_mma_kernel(float* __restrict__ out)
{
    __shared__ __align__(16) unsigned char sbuf[2][12288];
    const int tid = threadIdx.x, lane = tid & 31, wid = tid >> 5;
    const int b = blockIdx.z;
    const int m0 = blockIdx.y * 64;
    const int n0 = blockIdx.x * 128;
    const int wm = (wid >> 2) * 32;
    const int wn = (wid & 3) * 32;
    const uint32_t sb = smem_u32(&sbuf[0][0]);

    const __nv_bfloat16* Ah = g_fh + ((size_t)b * SEQ + m0) * HFB;
    const __nv_bfloat16* Al = g_fl + ((size_t)b * SEQ + m0) * HFB;
    const __nv_bfloat16* Bh = g_wh + (size_t)n0 * HFB;
    const __nv_bfloat16* Bl = g_wl + (size_t)n0 * HFB;

    float acc[2][4][4] = {};

    // issue one 16-k stage: A 256 chunks + B 512 chunks = 3/thread
    #define OUT_ISSUE(st, k0)                                                   \
        do {                                                                    \
            _Pragma("unroll")                                                   \
            for (int p = 0; p < 3; p++) {                                       \
                int id = tid + (p << 8);                                        \
                if (id < 256) {                                                 \
                    int r = id >> 2, cc = id & 3;                               \
                    const __nv_bfloat16* src = (cc < 2 ? Ah : Al)               \
                        + (size_t)r * HFB + (k0) + ((cc & 1) << 3);             \
                    uint32_t dst = sb + (st) * 12288 + r * 64                   \
                                 + ((cc ^ ((r >> 1) & 3)) << 4);                \
                    CP_ASYNC16(dst, src);                                       \
                } else {                                                        \
                    int rem = id - 256;                                         \
                    int r = rem >> 2, cc = rem & 3;                             \
                    const __nv_bfloat16* src = (cc < 2 ? Bh : Bl)               \
                        + (size_t)r * HFB + (k0) + ((cc & 1) << 3);             \
                    uint32_t dst = sb + (st) * 12288 + 4096 + r * 64            \
                                 + ((cc ^ ((r >> 1) & 3)) << 4);                \
                    CP_ASYNC16(dst, src);                                       \
                }                                                               \
            }                                                                   \
        } while (0)

    OUT_ISSUE(0, 0);
    CP_COMMIT();

    for (int s = 0; s < 128; s++) {
        if (s + 1 < 128) {
            OUT_ISSUE((s + 1) & 1, (s + 1) << 4);
            CP_COMMIT();
            CP_WAIT(1);
        } else {
            CP_WAIT(0);
        }
        __syncthreads();

        const uint32_t stb = sb + (uint32_t)(s & 1) * 12288;
        uint32_t ah[2][4], al[2][4], bhf[2][4], blf[2][4];
        lda_frag1(stb, wm,      lane, ah[0], al[0]);
        lda_frag1(stb, wm + 16, lane, ah[1], al[1]);
        ldb_frag(stb + 4096, wn, lane, bhf, blf);
        #pragma unroll
        for (int mi = 0; mi < 2; mi++)
            #pragma unroll
            for (int ni = 0; ni < 4; ni++) {
                const int g = ni >> 1, o = (ni & 1) << 1;
                MMA16816(acc[mi][ni], ah[mi], bhf[g][o], bhf[g][o + 1]);
                MMA16816(acc[mi][ni], ah[mi], blf[g][o], blf[g][o + 1]);
                MMA16816(acc[mi][ni], al[mi], bhf[g][o], bhf[g][o + 1]);
            }
        __syncthreads();
    }

    #pragma unroll
    for (int mi = 0; mi < 2; mi++) {
        #pragma unroll
        for (int ni = 0; ni < 4; ni++) {
            const int r0 = m0 + wm + mi * 16 + (lane >> 2);
            const int c  = n0 + wn + ni * 8 + ((lane & 3) << 1);
            *(float2*)(out + ((size_t)b * SEQ + r0) * FA + c) =
                make_float2(acc[mi][ni][0], acc[mi][ni][1]);
            *(float2*)(out + ((size_t)b * SEQ + r0 + 8) * FA + c) =
                make_float2(acc[mi][ni][2], acc[mi][ni][3]);
        }
    }
    #undef OUT_ISSUE
}

// ---------------- launch -----------------------------------------------------
extern "C" void kernel_launch(void* const* d_in, const int* in_sizes, int n_in,
                              void* d_out, int out_size)
{
    const float* z_a = (const float*)d_in[0];   // [2, 256, 2048]
    const float* z_b = (const float*)d_in[1];   // [2, 256, 2048]
    const float* W_a = (const float*)d_in[2];   // [512, 256]
    const float* W_b = (const float*)d_in[3];   // [512, 256]
    const float* W_c = (const float*)d_in[4];   // [256, 2048]
    float* out = (float*)d_out;                 // [2, 2048, 256] then l1 [2]
    float* l1  = out + (size_t)BATCH * SEQ * FA;

    cudaFuncSetAttribute(attn_fused_kernel,
                         cudaFuncAttributeMaxDynamicSharedMemorySize, SMEM_F2);

    zero_l1_kernel<<<1, 32>>>(l1);

    {
        const int nchunks = (BATCH * FB * SEQ + FA * HFB) / 4;
        conv_kernel<<<(nchunks + 255) / 256, 256>>>(z_b, W_c);
    }
    {
        dim3 grid(SEQ / BN, (NHEADS * EMB) / BM, BATCH * 2);
        embed_kernel<<<grid, 256>>>(W_a, z_a, W_b, z_b);
    }
    {
        dim3 grid(SEQ / 128, BATCH * NHEADS);
        attn_fused_kernel<<<grid, 256, SMEM_F2>>>(l1);
    }
    {
        dim3 grid(FA / 128, SEQ / 64, BATCH);
        out_mma_kernel<<<grid, 256>>>(out);
    }
}